// round 4
// baseline (speedup 1.0000x reference)
#include <cuda_runtime.h>
#include <cstdint>

// Problem shape (fixed for this dataset entry)
#define B_    2
#define N_    50000
#define C_    64
#define M_    50000
#define K_    16
#define H_    8
#define CMID_ 16

// Runtime-detected index width flag (int64 vs int32), set by detect kernel.
__device__ int g_idx_is64;

__global__ void detect_idx_kernel(const unsigned int* __restrict__ w) {
    if (threadIdx.x == 0 && blockIdx.x == 0) {
        int is64 = 1;
        #pragma unroll 1
        for (int i = 0; i < 256; i++) {
            if (w[2 * i + 1] != 0u) { is64 = 0; break; }
        }
        g_idx_is64 = is64;
    }
}

// One WARP per point; 4 points per 128-thread CTA.
// Lane l: cg = l&7 owns 8 CONTIGUOUS channels [8cg, 8cg+8) -> exactly ONE
// guidance head (head = c/8 = cg); jq = l>>3 owns w quad [4jq, 4jq+4).
// Thread tile: 8c x 4w = 32 outputs as 16 packed f32x2 (pairs along w).
// Per k (warp): 2 LDG.128 gather (4-dup) + 1 scalar guid LDS + ONE W LDS.128
// (vs 4 in R3 -- the L1-binding term) + 8 FMUL + dup movs + 16 fma.rn.f32x2.
__global__ void __launch_bounds__(128)
pcf_kernel(const float* __restrict__ feat,
           const void*  __restrict__ inds_raw,
           const float* __restrict__ guid,
           const float* __restrict__ wn,
           float* __restrict__ out)
{
    __shared__ __align__(16) float swn[4][K_ * CMID_];  // 4 x 1KB  weightnet
    __shared__ __align__(16) float sgd[4][K_ * H_];     // 4 x 512B guidance
    __shared__ int sidx[4][K_];

    const int wid  = threadIdx.x >> 5;
    const int lane = threadIdx.x & 31;
    const int p    = blockIdx.x * 4 + wid;      // point id in [0, B*M)
    const int b    = (p >= M_) ? 1 : 0;
    const int cg   = lane & 7;                  // channel group (== head)
    const int jq   = lane >> 3;                 // w quad 0..3

    // ---- per-warp staging: weightnet (1KB), guidance (512B), indices ----
    {
        const float4* wsrc = (const float4*)(wn + (size_t)p * (K_ * CMID_));
        float4* wdst = (float4*)(swn[wid]);
        wdst[lane]      = wsrc[lane];
        wdst[lane + 32] = wsrc[lane + 32];
        ((float4*)(sgd[wid]))[lane] = ((const float4*)(guid + (size_t)p * (K_ * H_)))[lane];
        if (lane < K_) {
            long long idx;
            if (g_idx_is64) idx = ((const long long*)inds_raw)[(size_t)p * K_ + lane];
            else            idx = (long long)((const int*)inds_raw)[(size_t)p * K_ + lane];
            sidx[wid][lane] = (int)idx;
        }
    }
    __syncwarp();

    // lane-fixed channel base: this lane's 8 channels start at 8*cg
    const float* fb = feat + (size_t)b * ((size_t)N_ * C_) + 8 * cg;

    // ---- 2-deep k-prefetch of the gather (2 x LDG.128 per k, MLP=4) ----
    float4 fq0[2], fq1[2];
    {
        const float* r0 = fb + (size_t)sidx[wid][0] * C_;
        const float* r1 = fb + (size_t)sidx[wid][1] * C_;
        fq0[0] = ((const float4*)r0)[0]; fq1[0] = ((const float4*)r0)[1];
        fq0[1] = ((const float4*)r1)[0]; fq1[1] = ((const float4*)r1)[1];
    }

    unsigned long long acc[16];
    #pragma unroll
    for (int i = 0; i < 16; i++) acc[i] = 0ull;

    #pragma unroll
    for (int k = 0; k < K_; k++) {
        float4 fa = fq0[k & 1];
        float4 fc = fq1[k & 1];
        if (k + 2 < K_) {
            const float* r = fb + (size_t)sidx[wid][k + 2] * C_;
            fq0[k & 1] = ((const float4*)r)[0];
            fq1[k & 1] = ((const float4*)r)[1];
        }

        const float g = sgd[wid][k * H_ + cg];  // single head per lane

        // W quad for this lane: 16B = {w0,w1,w2,w3} packed as 2 f32x2
        const ulonglong2 W = *(const ulonglong2*)(swn[wid] + k * CMID_ + jq * 4);

        float s0 = fa.x * g, s1 = fa.y * g, s2 = fa.z * g, s3 = fa.w * g;
        float s4 = fc.x * g, s5 = fc.y * g, s6 = fc.z * g, s7 = fc.w * g;
        unsigned long long d0, d1, d2, d3, d4, d5, d6, d7;
        asm("mov.b64 %0, {%1, %1};" : "=l"(d0) : "f"(s0));
        asm("mov.b64 %0, {%1, %1};" : "=l"(d1) : "f"(s1));
        asm("mov.b64 %0, {%1, %1};" : "=l"(d2) : "f"(s2));
        asm("mov.b64 %0, {%1, %1};" : "=l"(d3) : "f"(s3));
        asm("mov.b64 %0, {%1, %1};" : "=l"(d4) : "f"(s4));
        asm("mov.b64 %0, {%1, %1};" : "=l"(d5) : "f"(s5));
        asm("mov.b64 %0, {%1, %1};" : "=l"(d6) : "f"(s6));
        asm("mov.b64 %0, {%1, %1};" : "=l"(d7) : "f"(s7));

        asm("fma.rn.f32x2 %0, %1, %2, %3;" : "=l"(acc[ 0]) : "l"(d0), "l"(W.x), "l"(acc[ 0]));
        asm("fma.rn.f32x2 %0, %1, %2, %3;" : "=l"(acc[ 1]) : "l"(d0), "l"(W.y), "l"(acc[ 1]));
        asm("fma.rn.f32x2 %0, %1, %2, %3;" : "=l"(acc[ 2]) : "l"(d1), "l"(W.x), "l"(acc[ 2]));
        asm("fma.rn.f32x2 %0, %1, %2, %3;" : "=l"(acc[ 3]) : "l"(d1), "l"(W.y), "l"(acc[ 3]));
        asm("fma.rn.f32x2 %0, %1, %2, %3;" : "=l"(acc[ 4]) : "l"(d2), "l"(W.x), "l"(acc[ 4]));
        asm("fma.rn.f32x2 %0, %1, %2, %3;" : "=l"(acc[ 5]) : "l"(d2), "l"(W.y), "l"(acc[ 5]));
        asm("fma.rn.f32x2 %0, %1, %2, %3;" : "=l"(acc[ 6]) : "l"(d3), "l"(W.x), "l"(acc[ 6]));
        asm("fma.rn.f32x2 %0, %1, %2, %3;" : "=l"(acc[ 7]) : "l"(d3), "l"(W.y), "l"(acc[ 7]));
        asm("fma.rn.f32x2 %0, %1, %2, %3;" : "=l"(acc[ 8]) : "l"(d4), "l"(W.x), "l"(acc[ 8]));
        asm("fma.rn.f32x2 %0, %1, %2, %3;" : "=l"(acc[ 9]) : "l"(d4), "l"(W.y), "l"(acc[ 9]));
        asm("fma.rn.f32x2 %0, %1, %2, %3;" : "=l"(acc[10]) : "l"(d5), "l"(W.x), "l"(acc[10]));
        asm("fma.rn.f32x2 %0, %1, %2, %3;" : "=l"(acc[11]) : "l"(d5), "l"(W.y), "l"(acc[11]));
        asm("fma.rn.f32x2 %0, %1, %2, %3;" : "=l"(acc[12]) : "l"(d6), "l"(W.x), "l"(acc[12]));
        asm("fma.rn.f32x2 %0, %1, %2, %3;" : "=l"(acc[13]) : "l"(d6), "l"(W.y), "l"(acc[13]));
        asm("fma.rn.f32x2 %0, %1, %2, %3;" : "=l"(acc[14]) : "l"(d7), "l"(W.x), "l"(acc[14]));
        asm("fma.rn.f32x2 %0, %1, %2, %3;" : "=l"(acc[15]) : "l"(d7), "l"(W.y), "l"(acc[15]));
    }

    // ---- output: row c = 8*cg + i gets 16B {w=4jq .. 4jq+4} from acc[2i],acc[2i+1]
    float* o = out + (size_t)p * (C_ * CMID_) + (size_t)(8 * cg) * CMID_ + jq * 4;
    #pragma unroll
    for (int i = 0; i < 8; i++) {
        *(ulonglong2*)(o + i * CMID_) = make_ulonglong2(acc[2 * i], acc[2 * i + 1]);
    }
}

extern "C" void kernel_launch(void* const* d_in, const int* in_sizes, int n_in,
                              void* d_out, int out_size) {
    const float* feat = (const float*)d_in[0];
    const void*  inds = d_in[1];
    const float* guid = (const float*)d_in[2];
    const float* wn   = (const float*)d_in[3];
    float* out = (float*)d_out;

    detect_idx_kernel<<<1, 32>>>((const unsigned int*)inds);
    pcf_kernel<<<(B_ * M_) / 4, 128>>>(feat, inds, guid, wn, out);
}